// round 2
// baseline (speedup 1.0000x reference)
#include <cuda_runtime.h>
#include <math.h>

// Problem constants: B=32, N=1024, H=512  ->  M = 32768 rows, 2H = 1024
#define M_ROWS   32768
#define TWO_H    1024
#define H_DIM    512
#define DT_STEP  0.1f

// Scratch activations (allocation-free per harness rules): two ping-pong buffers.
__device__ float g_buf1[(size_t)M_ROWS * TWO_H];
__device__ float g_buf2[(size_t)M_ROWS * TWO_H];

constexpr int BM = 128, BN = 128, BK = 16, TM = 8, TN = 8;
constexpr int THREADS = (BM / TM) * (BN / TN);   // 256

// MODE_A: 0 = plain A [M,K] row-major; 1 = virtual concat(inp[M,512], hz[M,512])
template <int MODE_A>
__device__ __forceinline__ float4 fetchA4(const float* __restrict__ A,
                                          const float* __restrict__ A2,
                                          int grow, int gk, int K)
{
    if (MODE_A == 1) {
        if (gk < H_DIM)
            return __ldg(reinterpret_cast<const float4*>(A  + (size_t)grow * H_DIM + gk));
        else
            return __ldg(reinterpret_cast<const float4*>(A2 + (size_t)grow * H_DIM + (gk - H_DIM)));
    }
    return __ldg(reinterpret_cast<const float4*>(A + (size_t)grow * (size_t)K + gk));
}

// EPI: 0 = euler (out = h + DT*tanh(acc+bias)), 1 = relu(acc+bias), 2 = tanh(acc+bias)
template <int MODE_A, int EPI>
__global__ __launch_bounds__(THREADS, 2)
void gemm_fused(const float* __restrict__ A, const float* __restrict__ A2,
                const float* __restrict__ B, const float* __restrict__ bias,
                float* __restrict__ C, int M, int N, int K)
{
    __shared__ float As[BK][BM];   // transposed A tile: As[k][m]
    __shared__ float Bs[BK][BN];   // Bs[k][n]

    const int tid = threadIdx.x;
    const int tx  = tid % (BN / TN);   // 0..15
    const int ty  = tid / (BN / TN);   // 0..15
    const int rowBase = blockIdx.y * BM;
    const int colBase = blockIdx.x * BN;

    // Per-thread global-load coordinates (2 float4 each for A and B)
    // A tile: 128 rows x 16 cols = 512 float4; f -> row=f/4, col=(f%4)*4
    // B tile:  16 rows x 128 cols = 512 float4; f -> k=f/32,  n=(f%32)*4
    int aR[2], aC[2], bK[2], bN[2];
#pragma unroll
    for (int p = 0; p < 2; ++p) {
        int f = tid + p * THREADS;
        aR[p] = f >> 2;
        aC[p] = (f & 3) << 2;
        bK[p] = f >> 5;
        bN[p] = (f & 31) << 2;
    }

    float acc[TM][TN];
#pragma unroll
    for (int i = 0; i < TM; ++i)
#pragma unroll
        for (int j = 0; j < TN; ++j) acc[i][j] = 0.0f;

    const int numTiles = K / BK;

    // --- load tile 0 directly to smem ---
#pragma unroll
    for (int p = 0; p < 2; ++p) {
        float4 va = fetchA4<MODE_A>(A, A2, rowBase + aR[p], aC[p], K);
        As[aC[p] + 0][aR[p]] = va.x;
        As[aC[p] + 1][aR[p]] = va.y;
        As[aC[p] + 2][aR[p]] = va.z;
        As[aC[p] + 3][aR[p]] = va.w;
        float4 vb = __ldg(reinterpret_cast<const float4*>(
            B + (size_t)bK[p] * N + colBase + bN[p]));
        *reinterpret_cast<float4*>(&Bs[bK[p]][bN[p]]) = vb;
    }
    __syncthreads();

    float4 aFrag[2], bFrag[2];

    for (int kt = 0; kt < numTiles; ++kt) {
        // prefetch next tile into registers (hide global latency behind FFMAs)
        if (kt + 1 < numTiles) {
            int k0 = (kt + 1) * BK;
#pragma unroll
            for (int p = 0; p < 2; ++p) {
                aFrag[p] = fetchA4<MODE_A>(A, A2, rowBase + aR[p], k0 + aC[p], K);
                bFrag[p] = __ldg(reinterpret_cast<const float4*>(
                    B + (size_t)(k0 + bK[p]) * N + colBase + bN[p]));
            }
        }

        // compute on current tile
#pragma unroll
        for (int k = 0; k < BK; ++k) {
            float regM[TM], regN[TN];
            *reinterpret_cast<float4*>(&regM[0]) =
                *reinterpret_cast<const float4*>(&As[k][ty * TM + 0]);
            *reinterpret_cast<float4*>(&regM[4]) =
                *reinterpret_cast<const float4*>(&As[k][ty * TM + 4]);
            *reinterpret_cast<float4*>(&regN[0]) =
                *reinterpret_cast<const float4*>(&Bs[k][tx * TN + 0]);
            *reinterpret_cast<float4*>(&regN[4]) =
                *reinterpret_cast<const float4*>(&Bs[k][tx * TN + 4]);
#pragma unroll
            for (int i = 0; i < TM; ++i)
#pragma unroll
                for (int j = 0; j < TN; ++j)
                    acc[i][j] = fmaf(regM[i], regN[j], acc[i][j]);
        }
        __syncthreads();

        if (kt + 1 < numTiles) {
#pragma unroll
            for (int p = 0; p < 2; ++p) {
                As[aC[p] + 0][aR[p]] = aFrag[p].x;
                As[aC[p] + 1][aR[p]] = aFrag[p].y;
                As[aC[p] + 2][aR[p]] = aFrag[p].z;
                As[aC[p] + 3][aR[p]] = aFrag[p].w;
                *reinterpret_cast<float4*>(&Bs[bK[p]][bN[p]]) = bFrag[p];
            }
            __syncthreads();
        }
    }

    // --- fused epilogue ---
#pragma unroll
    for (int i = 0; i < TM; ++i) {
        const int grow = rowBase + ty * TM + i;
        float* crow = C + (size_t)grow * N + colBase + tx * TN;
#pragma unroll
        for (int jj = 0; jj < TN; jj += 4) {
            const int gcol = colBase + tx * TN + jj;
            float4 bi = __ldg(reinterpret_cast<const float4*>(bias + gcol));
            float v0 = acc[i][jj + 0] + bi.x;
            float v1 = acc[i][jj + 1] + bi.y;
            float v2 = acc[i][jj + 2] + bi.z;
            float v3 = acc[i][jj + 3] + bi.w;
            float4 r;
            if (EPI == 0) {
                // euler: out = h + DT * tanh(acc + bias); h read from the A source
                float4 h = fetchA4<MODE_A>(A, A2, grow, gcol, K);
                r.x = h.x + DT_STEP * tanhf(v0);
                r.y = h.y + DT_STEP * tanhf(v1);
                r.z = h.z + DT_STEP * tanhf(v2);
                r.w = h.w + DT_STEP * tanhf(v3);
            } else if (EPI == 1) {
                r.x = fmaxf(v0, 0.0f);
                r.y = fmaxf(v1, 0.0f);
                r.z = fmaxf(v2, 0.0f);
                r.w = fmaxf(v3, 0.0f);
            } else {
                r.x = tanhf(v0);
                r.y = tanhf(v1);
                r.z = tanhf(v2);
                r.w = tanhf(v3);
            }
            *reinterpret_cast<float4*>(crow + jj) = r;
        }
    }
}

extern "C" void kernel_launch(void* const* d_in, const int* in_sizes, int n_in,
                              void* d_out, int out_size)
{
    const float* inp = (const float*)d_in[0];   // [32, 1024, 512]
    const float* hz  = (const float*)d_in[1];   // [32, 1024, 512]
    const float* Wf  = (const float*)d_in[2];   // [1024, 1024]
    const float* bf  = (const float*)d_in[3];   // [1024]
    const float* W1  = (const float*)d_in[4];   // [1024, 1024]
    const float* b1  = (const float*)d_in[5];   // [1024]
    const float* W2  = (const float*)d_in[6];   // [1024, 512]
    const float* b2  = (const float*)d_in[7];   // [512]
    float* out = (float*)d_out;                 // [32, 1024, 512]

    float *buf1 = nullptr, *buf2 = nullptr;
    cudaGetSymbolAddress((void**)&buf1, g_buf1);
    cudaGetSymbolAddress((void**)&buf2, g_buf2);

    dim3 block(THREADS);
    dim3 gridSq(TWO_H / BN, M_ROWS / BM);   // (8, 256)
    dim3 gridOut(H_DIM / BN, M_ROWS / BM);  // (4, 256)

    // L1: euler step 1 on virtual concat(inp, hz) -> buf1
    gemm_fused<1, 0><<<gridSq, block>>>(inp, hz, Wf, bf, buf1,
                                        M_ROWS, TWO_H, TWO_H);
    // L2: euler step 2 -> buf2
    gemm_fused<0, 0><<<gridSq, block>>>(buf1, nullptr, Wf, bf, buf2,
                                        M_ROWS, TWO_H, TWO_H);
    // L3: relu(h @ W1 + b1) -> buf1
    gemm_fused<0, 1><<<gridSq, block>>>(buf2, nullptr, W1, b1, buf1,
                                        M_ROWS, TWO_H, TWO_H);
    // L4: tanh(h @ W2 + b2) -> out
    gemm_fused<0, 2><<<gridOut, block>>>(buf1, nullptr, W2, b2, out,
                                         M_ROWS, H_DIM, TWO_H);
}

// round 14
// speedup vs baseline: 2.4524x; 2.4524x over previous
#include <cuda_runtime.h>
#include <cuda_bf16.h>
#include <stdint.h>
#include <math.h>

// Problem: B=32, N=1024, H=512 -> M = 32768 rows, K = 1024 (2H)
#define M_ROWS  32768
#define TWO_H   1024
#define H_DIM   512
#define K_DIM   1024
#define DT_STEP 0.1f

// ---------------- scratch (__device__ globals; no allocations allowed) -----
__device__ float g_act1[(size_t)M_ROWS * TWO_H];
__device__ float g_act2[(size_t)M_ROWS * TWO_H];
__device__ __nv_bfloat16 g_wf_hi[TWO_H * TWO_H];
__device__ __nv_bfloat16 g_wf_lo[TWO_H * TWO_H];
__device__ __nv_bfloat16 g_w1_hi[TWO_H * TWO_H];
__device__ __nv_bfloat16 g_w1_lo[TWO_H * TWO_H];
__device__ __nv_bfloat16 g_w2_hi[H_DIM * TWO_H];
__device__ __nv_bfloat16 g_w2_lo[H_DIM * TWO_H];

// ---------------- PTX helpers (all baseline sm_80+, valid on compute_103) --
__device__ __forceinline__ uint32_t smem_u32(const void* p) {
    uint32_t a;
    asm("{ .reg .u64 t; cvta.to.shared.u64 t, %1; cvt.u32.u64 %0, t; }"
        : "=r"(a) : "l"(p));
    return a;
}
__device__ __forceinline__ void cp_async16(uint32_t dst, const void* src) {
    asm volatile("cp.async.cg.shared.global [%0], [%1], 16;"
                 :: "r"(dst), "l"(src) : "memory");
}
#define CP_COMMIT() asm volatile("cp.async.commit_group;" ::: "memory")
#define CP_WAIT0()  asm volatile("cp.async.wait_group 0;"  ::: "memory")

__device__ __forceinline__ void ldmx4(uint32_t& r0, uint32_t& r1,
                                      uint32_t& r2, uint32_t& r3, uint32_t a) {
    asm volatile("ldmatrix.sync.aligned.m8n8.x4.shared.b16 {%0,%1,%2,%3}, [%4];"
                 : "=r"(r0), "=r"(r1), "=r"(r2), "=r"(r3) : "r"(a));
}
__device__ __forceinline__ void mma16816(float* c, const uint32_t* a,
                                         const uint32_t* b) {
    asm volatile(
        "mma.sync.aligned.m16n8k16.row.col.f32.bf16.bf16.f32 "
        "{%0,%1,%2,%3}, {%4,%5,%6,%7}, {%8,%9}, {%0,%1,%2,%3};"
        : "+f"(c[0]), "+f"(c[1]), "+f"(c[2]), "+f"(c[3])
        : "r"(a[0]), "r"(a[1]), "r"(a[2]), "r"(a[3]), "r"(b[0]), "r"(b[1]));
}

// ---------------- GEMM config ----------------------------------------------
constexpr int BM = 128, BN = 128, KC = 32;     // CTA tile, K chunk
constexpr int THREADS = 256;                   // 8 warps: 2 (M) x 4 (N)
constexpr int NTILES = K_DIM / KC;             // 32
constexpr int PITCH = 80;                      // smem bytes/row: 64B data + 16B pad
constexpr int MAT_BYTES = 128 * PITCH;         // 10240 per matrix (A or B, hi or lo)
constexpr int OFF_A_HI = 0;
constexpr int OFF_A_LO = MAT_BYTES;
constexpr int OFF_B_HI = 2 * MAT_BYTES;
constexpr int OFF_B_LO = 3 * MAT_BYTES;
constexpr int STAGE = 4 * MAT_BYTES;           // 40960
constexpr int SMEM_TOTAL = 2 * STAGE;          // 81920

__device__ __forceinline__ uint32_t pack2(__nv_bfloat16 a, __nv_bfloat16 b) {
    union { __nv_bfloat16 h[2]; uint32_t u; } q;
    q.h[0] = a; q.h[1] = b;
    return q.u;
}

template <int MODE_A>
__device__ __forceinline__ float4 fetchA4(const float* __restrict__ A,
                                          const float* __restrict__ A2,
                                          int grow, int gk) {
    if (MODE_A == 1) {  // virtual concat(inp[.,512], hz[.,512])
        if (gk < H_DIM)
            return __ldg(reinterpret_cast<const float4*>(A + (size_t)grow * H_DIM + gk));
        return __ldg(reinterpret_cast<const float4*>(A2 + (size_t)grow * H_DIM + (gk - H_DIM)));
    }
    return __ldg(reinterpret_cast<const float4*>(A + (size_t)grow * K_DIM + gk));
}
template <int MODE_A>
__device__ __forceinline__ float2 fetchA2(const float* __restrict__ A,
                                          const float* __restrict__ A2,
                                          int grow, int gk) {
    if (MODE_A == 1) {
        if (gk < H_DIM)
            return __ldg(reinterpret_cast<const float2*>(A + (size_t)grow * H_DIM + gk));
        return __ldg(reinterpret_cast<const float2*>(A2 + (size_t)grow * H_DIM + (gk - H_DIM)));
    }
    return __ldg(reinterpret_cast<const float2*>(A + (size_t)grow * K_DIM + gk));
}

// EPI: 0 = euler (h + DT*tanh(acc+b)), 1 = relu, 2 = tanh
template <int MODE_A, int EPI>
__global__ void __launch_bounds__(THREADS, 1)
gemm_hmma(const float* __restrict__ A, const float* __restrict__ A2,
          const __nv_bfloat16* __restrict__ Bhi, const __nv_bfloat16* __restrict__ Blo,
          const float* __restrict__ bias, float* __restrict__ C, int N) {
    extern __shared__ char smem[];
    const uint32_t sb = smem_u32(smem);
    const int tid  = threadIdx.x;
    const int lane = tid & 31;
    const int warp = tid >> 5;
    const int wm = warp >> 2;          // 0..1  -> M offset wm*64
    const int wn = warp & 3;           // 0..3  -> N offset wn*32
    const int rowBase = blockIdx.y * BM;
    const int colBase = blockIdx.x * BN;

    // ---- per-thread staging coordinates ----
    // A: 128 rows x 32 K fp32 per stage = 512 chunks of 8 floats; 2 per thread
    int aRow[2], aKg[2];
#pragma unroll
    for (int c = 0; c < 2; ++c) {
        int id = tid + c * THREADS;
        aRow[c] = id >> 2;
        aKg[c]  = (id & 3) * 8;
    }
    // B: hi+lo, each 128 rows x 32 K bf16 = 512 16B chunks -> 1024 total; 4/thread
    float4 aReg[2][2];

    float acc[4][4][4];
#pragma unroll
    for (int i = 0; i < 4; ++i)
#pragma unroll
        for (int j = 0; j < 4; ++j)
#pragma unroll
            for (int f = 0; f < 4; ++f) acc[i][j][f] = 0.0f;

    auto loadA = [&](int kt) {
#pragma unroll
        for (int c = 0; c < 2; ++c) {
            aReg[c][0] = fetchA4<MODE_A>(A, A2, rowBase + aRow[c], kt * KC + aKg[c]);
            aReg[c][1] = fetchA4<MODE_A>(A, A2, rowBase + aRow[c], kt * KC + aKg[c] + 4);
        }
    };
    auto stsA = [&](int s) {
        uint32_t base = sb + s * STAGE;
#pragma unroll
        for (int c = 0; c < 2; ++c) {
            float xs[8] = {aReg[c][0].x, aReg[c][0].y, aReg[c][0].z, aReg[c][0].w,
                           aReg[c][1].x, aReg[c][1].y, aReg[c][1].z, aReg[c][1].w};
            __nv_bfloat16 h[8], l[8];
#pragma unroll
            for (int i = 0; i < 8; ++i) {
                h[i] = __float2bfloat16(xs[i]);
                l[i] = __float2bfloat16(xs[i] - __bfloat162float(h[i]));
            }
            uint32_t off = (uint32_t)aRow[c] * PITCH + aKg[c] * 2;
            uint4 hp = make_uint4(pack2(h[0], h[1]), pack2(h[2], h[3]),
                                  pack2(h[4], h[5]), pack2(h[6], h[7]));
            uint4 lp = make_uint4(pack2(l[0], l[1]), pack2(l[2], l[3]),
                                  pack2(l[4], l[5]), pack2(l[6], l[7]));
            asm volatile("st.shared.v4.b32 [%0], {%1,%2,%3,%4};"
                         :: "r"(base + OFF_A_HI + off),
                            "r"(hp.x), "r"(hp.y), "r"(hp.z), "r"(hp.w) : "memory");
            asm volatile("st.shared.v4.b32 [%0], {%1,%2,%3,%4};"
                         :: "r"(base + OFF_A_LO + off),
                            "r"(lp.x), "r"(lp.y), "r"(lp.z), "r"(lp.w) : "memory");
        }
    };
    auto cpB = [&](int s, int kt) {
        uint32_t base = sb + s * STAGE;
#pragma unroll
        for (int c = 0; c < 4; ++c) {
            int id  = tid + c * THREADS;        // 0..1023
            int hl  = id >> 9;                  // 0 = hi, 1 = lo
            int rem = id & 511;
            int row = rem >> 2;
            int kg  = rem & 3;
            const __nv_bfloat16* src =
                (hl ? Blo : Bhi) + (size_t)(colBase + row) * K_DIM + kt * KC + kg * 8;
            uint32_t dst = base + (hl ? OFF_B_LO : OFF_B_HI)
                         + (uint32_t)row * PITCH + kg * 16;
            cp_async16(dst, src);
        }
        CP_COMMIT();
    };

    auto compute = [&](int s) {
        const uint32_t base = sb + s * STAGE;
        const int lr = lane & 7;
        const int lh = (lane >> 3) & 1;
        const int lq = lane >> 4;
        const int bmat = lane >> 3;            // 0..3
#pragma unroll
        for (int ks = 0; ks < 2; ++ks) {       // two k16 steps in KC=32
            uint32_t aHi[4][4], aLo[4][4];
#pragma unroll
            for (int i = 0; i < 4; ++i) {
                uint32_t off = (uint32_t)(wm * 64 + i * 16 + lr + lh * 8) * PITCH
                             + ks * 32 + lq * 16;
                ldmx4(aHi[i][0], aHi[i][1], aHi[i][2], aHi[i][3], base + OFF_A_HI + off);
                ldmx4(aLo[i][0], aLo[i][1], aLo[i][2], aLo[i][3], base + OFF_A_LO + off);
            }
            uint32_t bHi[4][2], bLo[4][2];
#pragma unroll
            for (int g = 0; g < 2; ++g) {
                uint32_t off = (uint32_t)(wn * 32 + g * 16 + lr + (bmat >> 1) * 8) * PITCH
                             + (bmat & 1) * 16 + ks * 32;
                uint32_t t0, t1, t2, t3;
                ldmx4(t0, t1, t2, t3, base + OFF_B_HI + off);
                bHi[2 * g][0] = t0; bHi[2 * g][1] = t1;
                bHi[2 * g + 1][0] = t2; bHi[2 * g + 1][1] = t3;
                ldmx4(t0, t1, t2, t3, base + OFF_B_LO + off);
                bLo[2 * g][0] = t0; bLo[2 * g][1] = t1;
                bLo[2 * g + 1][0] = t2; bLo[2 * g + 1][1] = t3;
            }
            // term-major ordering: same accumulator reused only every 16 MMAs
#pragma unroll
            for (int i = 0; i < 4; ++i)
#pragma unroll
                for (int j = 0; j < 4; ++j)
                    mma16816(acc[i][j], aHi[i], bHi[j]);
#pragma unroll
            for (int i = 0; i < 4; ++i)
#pragma unroll
                for (int j = 0; j < 4; ++j)
                    mma16816(acc[i][j], aHi[i], bLo[j]);
#pragma unroll
            for (int i = 0; i < 4; ++i)
#pragma unroll
                for (int j = 0; j < 4; ++j)
                    mma16816(acc[i][j], aLo[i], bHi[j]);
        }
    };

    // ---- prologue: stage 0 ----
    loadA(0);
    cpB(0, 0);
    stsA(0);
    CP_WAIT0();
    __syncthreads();

    // ---- main loop, double buffered ----
    for (int kt = 0; kt < NTILES; ++kt) {
        const int cur = kt & 1;
        const bool more = (kt + 1) < NTILES;
        if (more) {
            loadA(kt + 1);             // LDG in flight during compute
            cpB(cur ^ 1, kt + 1);      // async B copy into next stage
        }
        compute(cur);
        if (more) {
            stsA(cur ^ 1);             // LDGs have landed by now
            CP_WAIT0();
        }
        __syncthreads();
    }

    // ---- fused epilogue ----
#pragma unroll
    for (int i = 0; i < 4; ++i) {
        const int r0 = rowBase + wm * 64 + i * 16 + (lane >> 2);
#pragma unroll
        for (int j = 0; j < 4; ++j) {
            const int c0 = colBase + wn * 32 + j * 8 + (lane & 3) * 2;
            float2 bi = __ldg(reinterpret_cast<const float2*>(bias + c0));
#pragma unroll
            for (int hrow = 0; hrow < 2; ++hrow) {
                const int r = r0 + hrow * 8;
                float v0 = acc[i][j][hrow * 2 + 0] + bi.x;
                float v1 = acc[i][j][hrow * 2 + 1] + bi.y;
                float2 o;
                if (EPI == 0) {
                    float2 h = fetchA2<MODE_A>(A, A2, r, c0);
                    o.x = h.x + DT_STEP * tanhf(v0);
                    o.y = h.y + DT_STEP * tanhf(v1);
                } else if (EPI == 1) {
                    o.x = fmaxf(v0, 0.0f);
                    o.y = fmaxf(v1, 0.0f);
                } else {
                    o.x = tanhf(v0);
                    o.y = tanhf(v1);
                }
                *reinterpret_cast<float2*>(C + (size_t)r * N + c0) = o;
            }
        }
    }
}

// W [K,N] fp32 -> Wt_hi/lo [N,K] bf16 (transposed, hi/lo split)
__global__ void convert_weights(const float* __restrict__ W,
                                __nv_bfloat16* __restrict__ hi,
                                __nv_bfloat16* __restrict__ lo,
                                int K, int N) {
    int idx = blockIdx.x * blockDim.x + threadIdx.x;
    if (idx >= K * N) return;
    int n = idx / K;
    int k = idx - n * K;
    float x = W[(size_t)k * N + n];
    __nv_bfloat16 h = __float2bfloat16(x);
    hi[idx] = h;
    lo[idx] = __float2bfloat16(x - __bfloat162float(h));
}

extern "C" void kernel_launch(void* const* d_in, const int* in_sizes, int n_in,
                              void* d_out, int out_size) {
    const float* inp = (const float*)d_in[0];
    const float* hz  = (const float*)d_in[1];
    const float* Wf  = (const float*)d_in[2];
    const float* bf  = (const float*)d_in[3];
    const float* W1  = (const float*)d_in[4];
    const float* b1  = (const float*)d_in[5];
    const float* W2  = (const float*)d_in[6];
    const float* b2  = (const float*)d_in[7];
    float* out = (float*)d_out;

    float *act1, *act2;
    __nv_bfloat16 *wf_hi, *wf_lo, *w1_hi, *w1_lo, *w2_hi, *w2_lo;
    cudaGetSymbolAddress((void**)&act1, g_act1);
    cudaGetSymbolAddress((void**)&act2, g_act2);
    cudaGetSymbolAddress((void**)&wf_hi, g_wf_hi);
    cudaGetSymbolAddress((void**)&wf_lo, g_wf_lo);
    cudaGetSymbolAddress((void**)&w1_hi, g_w1_hi);
    cudaGetSymbolAddress((void**)&w1_lo, g_w1_lo);
    cudaGetSymbolAddress((void**)&w2_hi, g_w2_hi);
    cudaGetSymbolAddress((void**)&w2_lo, g_w2_lo);

    cudaFuncSetAttribute(gemm_hmma<1, 0>, cudaFuncAttributeMaxDynamicSharedMemorySize, SMEM_TOTAL);
    cudaFuncSetAttribute(gemm_hmma<0, 0>, cudaFuncAttributeMaxDynamicSharedMemorySize, SMEM_TOTAL);
    cudaFuncSetAttribute(gemm_hmma<0, 1>, cudaFuncAttributeMaxDynamicSharedMemorySize, SMEM_TOTAL);
    cudaFuncSetAttribute(gemm_hmma<0, 2>, cudaFuncAttributeMaxDynamicSharedMemorySize, SMEM_TOTAL);

    // weight conversion (transposed hi/lo split)
    {
        int n1 = TWO_H * TWO_H, n2 = H_DIM * TWO_H;
        convert_weights<<<(n1 + 255) / 256, 256>>>(Wf, wf_hi, wf_lo, K_DIM, TWO_H);
        convert_weights<<<(n1 + 255) / 256, 256>>>(W1, w1_hi, w1_lo, K_DIM, TWO_H);
        convert_weights<<<(n2 + 255) / 256, 256>>>(W2, w2_hi, w2_lo, K_DIM, H_DIM);
    }

    dim3 block(THREADS);
    dim3 gridSq(TWO_H / BN, M_ROWS / BM);   // (8, 256)
    dim3 gridOut(H_DIM / BN, M_ROWS / BM);  // (4, 256)

    // L1: euler step 1 on concat(inp, hz) -> act1
    gemm_hmma<1, 0><<<gridSq, block, SMEM_TOTAL>>>(inp, hz, wf_hi, wf_lo, bf, act1, TWO_H);
    // L2: euler step 2 -> act2
    gemm_hmma<0, 0><<<gridSq, block, SMEM_TOTAL>>>(act1, nullptr, wf_hi, wf_lo, bf, act2, TWO_H);
    // L3: relu(h @ W1 + b1) -> act1
    gemm_hmma<0, 1><<<gridSq, block, SMEM_TOTAL>>>(act2, nullptr, w1_hi, w1_lo, b1, act1, TWO_H);
    // L4: tanh(h @ W2 + b2) -> out
    gemm_hmma<0, 2><<<gridOut, block, SMEM_TOTAL>>>(act1, nullptr, w2_hi, w2_lo, b2, out, H_DIM);
}

// round 17
// speedup vs baseline: 2.4558x; 1.0014x over previous
#include <cuda_runtime.h>
#include <cuda_bf16.h>
#include <stdint.h>
#include <math.h>

// Problem: B=32, N=1024, H=512 -> M = 32768 rows, K = 1024 (2H)
#define M_ROWS  32768
#define TWO_H   1024
#define H_DIM   512
#define K_DIM   1024
#define DT_STEP 0.1f

// ---------------- scratch (__device__ globals; no allocations allowed) -----
__device__ float g_act1[(size_t)M_ROWS * TWO_H];
__device__ float g_act2[(size_t)M_ROWS * TWO_H];
__device__ __nv_bfloat16 g_wf_hi[TWO_H * TWO_H];
__device__ __nv_bfloat16 g_wf_lo[TWO_H * TWO_H];
__device__ __nv_bfloat16 g_w1_hi[TWO_H * TWO_H];
__device__ __nv_bfloat16 g_w1_lo[TWO_H * TWO_H];
__device__ __nv_bfloat16 g_w2_hi[H_DIM * TWO_H];
__device__ __nv_bfloat16 g_w2_lo[H_DIM * TWO_H];

// ---------------- PTX helpers (all baseline sm_80+, valid on compute_103) --
__device__ __forceinline__ uint32_t smem_u32(const void* p) {
    uint32_t a;
    asm("{ .reg .u64 t; cvta.to.shared.u64 t, %1; cvt.u32.u64 %0, t; }"
        : "=r"(a) : "l"(p));
    return a;
}
__device__ __forceinline__ void cp_async16(uint32_t dst, const void* src) {
    asm volatile("cp.async.cg.shared.global [%0], [%1], 16;"
                 :: "r"(dst), "l"(src) : "memory");
}
#define CP_COMMIT() asm volatile("cp.async.commit_group;" ::: "memory")
#define CP_WAIT0()  asm volatile("cp.async.wait_group 0;"  ::: "memory")

__device__ __forceinline__ void ldmx4(uint32_t& r0, uint32_t& r1,
                                      uint32_t& r2, uint32_t& r3, uint32_t a) {
    asm volatile("ldmatrix.sync.aligned.m8n8.x4.shared.b16 {%0,%1,%2,%3}, [%4];"
                 : "=r"(r0), "=r"(r1), "=r"(r2), "=r"(r3) : "r"(a));
}
__device__ __forceinline__ void mma16816(float* c, const uint32_t* a,
                                         const uint32_t* b) {
    asm volatile(
        "mma.sync.aligned.m16n8k16.row.col.f32.bf16.bf16.f32 "
        "{%0,%1,%2,%3}, {%4,%5,%6,%7}, {%8,%9}, {%0,%1,%2,%3};"
        : "+f"(c[0]), "+f"(c[1]), "+f"(c[2]), "+f"(c[3])
        : "r"(a[0]), "r"(a[1]), "r"(a[2]), "r"(a[3]), "r"(b[0]), "r"(b[1]));
}

// ---------------- GEMM config ----------------------------------------------
constexpr int BM = 128, BN = 128, KC = 32;     // CTA tile, K chunk
constexpr int THREADS = 256;                   // 8 warps: 2 (M) x 4 (N)
constexpr int NTILES = K_DIM / KC;             // 32
constexpr int PITCH = 80;                      // smem bytes/row: 64B data + 16B pad
constexpr int MAT_BYTES = 128 * PITCH;         // 10240 per matrix (A or B, hi or lo)
constexpr int OFF_A_HI = 0;
constexpr int OFF_A_LO = MAT_BYTES;
constexpr int OFF_B_HI = 2 * MAT_BYTES;
constexpr int OFF_B_LO = 3 * MAT_BYTES;
constexpr int STAGE = 4 * MAT_BYTES;           // 40960
constexpr int SMEM_TOTAL = 2 * STAGE;          // 81920

__device__ __forceinline__ uint32_t pack2(__nv_bfloat16 a, __nv_bfloat16 b) {
    union { __nv_bfloat16 h[2]; uint32_t u; } q;
    q.h[0] = a; q.h[1] = b;
    return q.u;
}

template <int MODE_A>
__device__ __forceinline__ float4 fetchA4(const float* __restrict__ A,
                                          const float* __restrict__ A2,
                                          int grow, int gk) {
    if (MODE_A == 1) {  // virtual concat(inp[.,512], hz[.,512])
        if (gk < H_DIM)
            return __ldg(reinterpret_cast<const float4*>(A + (size_t)grow * H_DIM + gk));
        return __ldg(reinterpret_cast<const float4*>(A2 + (size_t)grow * H_DIM + (gk - H_DIM)));
    }
    return __ldg(reinterpret_cast<const float4*>(A + (size_t)grow * K_DIM + gk));
}
template <int MODE_A>
__device__ __forceinline__ float2 fetchA2(const float* __restrict__ A,
                                          const float* __restrict__ A2,
                                          int grow, int gk) {
    if (MODE_A == 1) {
        if (gk < H_DIM)
            return __ldg(reinterpret_cast<const float2*>(A + (size_t)grow * H_DIM + gk));
        return __ldg(reinterpret_cast<const float2*>(A2 + (size_t)grow * H_DIM + (gk - H_DIM)));
    }
    return __ldg(reinterpret_cast<const float2*>(A + (size_t)grow * K_DIM + gk));
}

// EPI: 0 = euler (h + DT*tanh(acc+b)), 1 = relu, 2 = tanh
template <int MODE_A, int EPI>
__global__ void __launch_bounds__(THREADS, 1)
gemm_hmma(const float* __restrict__ A, const float* __restrict__ A2,
          const __nv_bfloat16* __restrict__ Bhi, const __nv_bfloat16* __restrict__ Blo,
          const float* __restrict__ bias, float* __restrict__ C, int N) {
    extern __shared__ char smem[];
    const uint32_t sb = smem_u32(smem);
    const int tid  = threadIdx.x;
    const int lane = tid & 31;
    const int warp = tid >> 5;
    const int wm = warp >> 2;          // 0..1  -> M offset wm*64
    const int wn = warp & 3;           // 0..3  -> N offset wn*32
    const int rowBase = blockIdx.y * BM;
    const int colBase = blockIdx.x * BN;

    // ---- per-thread staging coordinates ----
    // A: 128 rows x 32 K fp32 per stage = 512 chunks of 8 floats; 2 per thread
    int aRow[2], aKg[2];
#pragma unroll
    for (int c = 0; c < 2; ++c) {
        int id = tid + c * THREADS;
        aRow[c] = id >> 2;
        aKg[c]  = (id & 3) * 8;
    }
    // B: hi+lo, each 128 rows x 32 K bf16 = 512 16B chunks -> 1024 total; 4/thread
    float4 aReg[2][2];

    float acc[4][4][4];
#pragma unroll
    for (int i = 0; i < 4; ++i)
#pragma unroll
        for (int j = 0; j < 4; ++j)
#pragma unroll
            for (int f = 0; f < 4; ++f) acc[i][j][f] = 0.0f;

    auto loadA = [&](int kt) {
#pragma unroll
        for (int c = 0; c < 2; ++c) {
            aReg[c][0] = fetchA4<MODE_A>(A, A2, rowBase + aRow[c], kt * KC + aKg[c]);
            aReg[c][1] = fetchA4<MODE_A>(A, A2, rowBase + aRow[c], kt * KC + aKg[c] + 4);
        }
    };
    auto stsA = [&](int s) {
        uint32_t base = sb + s * STAGE;
#pragma unroll
        for (int c = 0; c < 2; ++c) {
            float xs[8] = {aReg[c][0].x, aReg[c][0].y, aReg[c][0].z, aReg[c][0].w,
                           aReg[c][1].x, aReg[c][1].y, aReg[c][1].z, aReg[c][1].w};
            __nv_bfloat16 h[8], l[8];
#pragma unroll
            for (int i = 0; i < 8; ++i) {
                h[i] = __float2bfloat16(xs[i]);
                l[i] = __float2bfloat16(xs[i] - __bfloat162float(h[i]));
            }
            uint32_t off = (uint32_t)aRow[c] * PITCH + aKg[c] * 2;
            uint4 hp = make_uint4(pack2(h[0], h[1]), pack2(h[2], h[3]),
                                  pack2(h[4], h[5]), pack2(h[6], h[7]));
            uint4 lp = make_uint4(pack2(l[0], l[1]), pack2(l[2], l[3]),
                                  pack2(l[4], l[5]), pack2(l[6], l[7]));
            asm volatile("st.shared.v4.b32 [%0], {%1,%2,%3,%4};"
                         :: "r"(base + OFF_A_HI + off),
                            "r"(hp.x), "r"(hp.y), "r"(hp.z), "r"(hp.w) : "memory");
            asm volatile("st.shared.v4.b32 [%0], {%1,%2,%3,%4};"
                         :: "r"(base + OFF_A_LO + off),
                            "r"(lp.x), "r"(lp.y), "r"(lp.z), "r"(lp.w) : "memory");
        }
    };
    auto cpB = [&](int s, int kt) {
        uint32_t base = sb + s * STAGE;
#pragma unroll
        for (int c = 0; c < 4; ++c) {
            int id  = tid + c * THREADS;        // 0..1023
            int hl  = id >> 9;                  // 0 = hi, 1 = lo
            int rem = id & 511;
            int row = rem >> 2;
            int kg  = rem & 3;
            const __nv_bfloat16* src =
                (hl ? Blo : Bhi) + (size_t)(colBase + row) * K_DIM + kt * KC + kg * 8;
            uint32_t dst = base + (hl ? OFF_B_LO : OFF_B_HI)
                         + (uint32_t)row * PITCH + kg * 16;
            cp_async16(dst, src);
        }
        CP_COMMIT();
    };

    auto compute = [&](int s) {
        const uint32_t base = sb + s * STAGE;
        const int lr = lane & 7;
        const int lh = (lane >> 3) & 1;
        const int lq = lane >> 4;
        const int bmat = lane >> 3;            // 0..3
#pragma unroll
        for (int ks = 0; ks < 2; ++ks) {       // two k16 steps in KC=32
            uint32_t aHi[4][4], aLo[4][4];
#pragma unroll
            for (int i = 0; i < 4; ++i) {
                uint32_t off = (uint32_t)(wm * 64 + i * 16 + lr + lh * 8) * PITCH
                             + ks * 32 + lq * 16;
                ldmx4(aHi[i][0], aHi[i][1], aHi[i][2], aHi[i][3], base + OFF_A_HI + off);
                ldmx4(aLo[i][0], aLo[i][1], aLo[i][2], aLo[i][3], base + OFF_A_LO + off);
            }
            uint32_t bHi[4][2], bLo[4][2];
#pragma unroll
            for (int g = 0; g < 2; ++g) {
                uint32_t off = (uint32_t)(wn * 32 + g * 16 + lr + (bmat >> 1) * 8) * PITCH
                             + (bmat & 1) * 16 + ks * 32;
                uint32_t t0, t1, t2, t3;
                ldmx4(t0, t1, t2, t3, base + OFF_B_HI + off);
                bHi[2 * g][0] = t0; bHi[2 * g][1] = t1;
                bHi[2 * g + 1][0] = t2; bHi[2 * g + 1][1] = t3;
                ldmx4(t0, t1, t2, t3, base + OFF_B_LO + off);
                bLo[2 * g][0] = t0; bLo[2 * g][1] = t1;
                bLo[2 * g + 1][0] = t2; bLo[2 * g + 1][1] = t3;
            }
            // term-major ordering: same accumulator reused only every 16 MMAs
#pragma unroll
            for (int i = 0; i < 4; ++i)
#pragma unroll
                for (int j = 0; j < 4; ++j)
                    mma16816(acc[i][j], aHi[i], bHi[j]);
#pragma unroll
            for (int i = 0; i < 4; ++i)
#pragma unroll
                for (int j = 0; j < 4; ++j)
                    mma16816(acc[i][j], aHi[i], bLo[j]);
#pragma unroll
            for (int i = 0; i < 4; ++i)
#pragma unroll
                for (int j = 0; j < 4; ++j)
                    mma16816(acc[i][j], aLo[i], bHi[j]);
        }
    };

    // ---- prologue: stage 0 ----
    loadA(0);
    cpB(0, 0);
    stsA(0);
    CP_WAIT0();
    __syncthreads();

    // ---- main loop, double buffered ----
    for (int kt = 0; kt < NTILES; ++kt) {
        const int cur = kt & 1;
        const bool more = (kt + 1) < NTILES;
        if (more) {
            loadA(kt + 1);             // LDG in flight during compute
            cpB(cur ^ 1, kt + 1);      // async B copy into next stage
        }
        compute(cur);
        if (more) {
            stsA(cur ^ 1);             // LDGs have landed by now
            CP_WAIT0();
        }
        __syncthreads();
    }

    // ---- fused epilogue ----
#pragma unroll
    for (int i = 0; i < 4; ++i) {
        const int r0 = rowBase + wm * 64 + i * 16 + (lane >> 2);
#pragma unroll
        for (int j = 0; j < 4; ++j) {
            const int c0 = colBase + wn * 32 + j * 8 + (lane & 3) * 2;
            float2 bi = __ldg(reinterpret_cast<const float2*>(bias + c0));
#pragma unroll
            for (int hrow = 0; hrow < 2; ++hrow) {
                const int r = r0 + hrow * 8;
                float v0 = acc[i][j][hrow * 2 + 0] + bi.x;
                float v1 = acc[i][j][hrow * 2 + 1] + bi.y;
                float2 o;
                if (EPI == 0) {
                    float2 h = fetchA2<MODE_A>(A, A2, r, c0);
                    o.x = h.x + DT_STEP * tanhf(v0);
                    o.y = h.y + DT_STEP * tanhf(v1);
                } else if (EPI == 1) {
                    o.x = fmaxf(v0, 0.0f);
                    o.y = fmaxf(v1, 0.0f);
                } else {
                    o.x = tanhf(v0);
                    o.y = tanhf(v1);
                }
                *reinterpret_cast<float2*>(C + (size_t)r * N + c0) = o;
            }
        }
    }
}

// W [K,N] fp32 -> Wt_hi/lo [N,K] bf16 (transposed, hi/lo split)
__global__ void convert_weights(const float* __restrict__ W,
                                __nv_bfloat16* __restrict__ hi,
                                __nv_bfloat16* __restrict__ lo,
                                int K, int N) {
    int idx = blockIdx.x * blockDim.x + threadIdx.x;
    if (idx >= K * N) return;
    int n = idx / K;
    int k = idx - n * K;
    float x = W[(size_t)k * N + n];
    __nv_bfloat16 h = __float2bfloat16(x);
    hi[idx] = h;
    lo[idx] = __float2bfloat16(x - __bfloat162float(h));
}

extern "C" void kernel_launch(void* const* d_in, const int* in_sizes, int n_in,
                              void* d_out, int out_size) {
    const float* inp = (const float*)d_in[0];
    const float* hz  = (const float*)d_in[1];
    const float* Wf  = (const float*)d_in[2];
    const float* bf  = (const float*)d_in[3];
    const float* W1  = (const float*)d_in[4];
    const float* b1  = (const float*)d_in[5];
    const float* W2  = (const float*)d_in[6];
    const float* b2  = (const float*)d_in[7];
    float* out = (float*)d_out;

    float *act1, *act2;
    __nv_bfloat16 *wf_hi, *wf_lo, *w1_hi, *w1_lo, *w2_hi, *w2_lo;
    cudaGetSymbolAddress((void**)&act1, g_act1);
    cudaGetSymbolAddress((void**)&act2, g_act2);
    cudaGetSymbolAddress((void**)&wf_hi, g_wf_hi);
    cudaGetSymbolAddress((void**)&wf_lo, g_wf_lo);
    cudaGetSymbolAddress((void**)&w1_hi, g_w1_hi);
    cudaGetSymbolAddress((void**)&w1_lo, g_w1_lo);
    cudaGetSymbolAddress((void**)&w2_hi, g_w2_hi);
    cudaGetSymbolAddress((void**)&w2_lo, g_w2_lo);

    cudaFuncSetAttribute(gemm_hmma<1, 0>, cudaFuncAttributeMaxDynamicSharedMemorySize, SMEM_TOTAL);
    cudaFuncSetAttribute(gemm_hmma<0, 0>, cudaFuncAttributeMaxDynamicSharedMemorySize, SMEM_TOTAL);
    cudaFuncSetAttribute(gemm_hmma<0, 1>, cudaFuncAttributeMaxDynamicSharedMemorySize, SMEM_TOTAL);
    cudaFuncSetAttribute(gemm_hmma<0, 2>, cudaFuncAttributeMaxDynamicSharedMemorySize, SMEM_TOTAL);

    // weight conversion (transposed hi/lo split)
    {
        int n1 = TWO_H * TWO_H, n2 = H_DIM * TWO_H;
        convert_weights<<<(n1 + 255) / 256, 256>>>(Wf, wf_hi, wf_lo, K_DIM, TWO_H);
        convert_weights<<<(n1 + 255) / 256, 256>>>(W1, w1_hi, w1_lo, K_DIM, TWO_H);
        convert_weights<<<(n2 + 255) / 256, 256>>>(W2, w2_hi, w2_lo, K_DIM, H_DIM);
    }

    dim3 block(THREADS);
    dim3 gridSq(TWO_H / BN, M_ROWS / BM);   // (8, 256)
    dim3 gridOut(H_DIM / BN, M_ROWS / BM);  // (4, 256)

    // L1: euler step 1 on concat(inp, hz) -> act1
    gemm_hmma<1, 0><<<gridSq, block, SMEM_TOTAL>>>(inp, hz, wf_hi, wf_lo, bf, act1, TWO_H);
    // L2: euler step 2 -> act2
    gemm_hmma<0, 0><<<gridSq, block, SMEM_TOTAL>>>(act1, nullptr, wf_hi, wf_lo, bf, act2, TWO_H);
    // L3: relu(h @ W1 + b1) -> act1
    gemm_hmma<0, 1><<<gridSq, block, SMEM_TOTAL>>>(act2, nullptr, w1_hi, w1_lo, b1, act1, TWO_H);
    // L4: tanh(h @ W2 + b2) -> out
    gemm_hmma<0, 2><<<gridOut, block, SMEM_TOTAL>>>(act1, nullptr, w2_hi, w2_lo, b2, out, H_DIM);
}